// round 16
// baseline (speedup 1.0000x reference)
#include <cuda_runtime.h>
#include <cuda_fp16.h>
#include <cuda_bf16.h>
#include <mma.h>
#include <cstdint>

using namespace nvcuda;

#define N_NODES 50000
#define N_EDGES 800000
#define IN_DIM  128
#define HID_DIM 128
#define OUT_DIM 64

#define SCAN_BS   512
#define SCAN_NB   ((N_NODES + SCAN_BS - 1) / SCAN_BS)   // 98
#define BUILD_T   (SCAN_NB * SCAN_BS)                    // 50176 threads grid-wide

// ---------------- scratch (device globals: no allocation allowed) -------------
// Only referenced from DEVICE code (R5 lesson).
// Cross-call invariants (graph replays run the identical sequence):
//   g_degi  : zero at load; build phase-2 re-zeroes after reading.
//   g_state : build resets its own slot at kernel start (before barrier 1).
//   g_barctr/g_barrel : monotonic epoch barrier; never reset.
__device__ __align__(16) int                g_degi    [N_NODES];
__device__ __align__(16) float              g_dinv    [N_NODES];
__device__ __align__(16) int                g_rowstart[N_NODES + 1];
__device__ __align__(16) int                g_rank    [N_EDGES];
__device__ __align__(16) int                g_csr     [N_EDGES];
__device__ __align__(16) unsigned long long g_state   [SCAN_NB];
__device__ unsigned g_barctr[2];
__device__ unsigned g_barrel[2];
__device__ __align__(16) __half             g_xwh     [N_NODES * HID_DIM];  // x@W1, fp16
__device__ __align__(16) float              g_c2      [HID_DIM * 2];        // W2 @ Wfc
__device__ __align__(16) float              g_cbias   [2];                  // b2@Wfc + bfc
__device__ __align__(16) float              g_z       [N_NODES * 2];

// ---------------- helpers -------------------------------------------------------
// load 8 halves (16B, LDG.128) and widen to 8 floats
__device__ __forceinline__ void ldg_half8(const __half* p, float* f) {
    uint4 u = __ldg(reinterpret_cast<const uint4*>(p));
    __half2* h = reinterpret_cast<__half2*>(&u);
    float2 a = __half22float2(h[0]);
    float2 b = __half22float2(h[1]);
    float2 c = __half22float2(h[2]);
    float2 d = __half22float2(h[3]);
    f[0] = a.x; f[1] = a.y; f[2] = b.x; f[3] = b.y;
    f[4] = c.x; f[5] = c.y; f[6] = d.x; f[7] = d.y;
}

// monotonic epoch grid barrier: replay-safe (no resets), deadlock-free for
// co-resident grids (98 blocks <= 148 SMs).
__device__ __forceinline__ void grid_barrier(int i) {
    __syncthreads();
    if (threadIdx.x == 0) {
        __threadfence();
        unsigned old = atomicAdd(&g_barctr[i], 1u);
        unsigned epoch = old / SCAN_NB;
        if (old % SCAN_NB == SCAN_NB - 1) {
            atomicAdd(&g_barrel[i], 1u);               // release this epoch
        } else {
            while (*(volatile unsigned*)&g_barrel[i] <= epoch) __nanosleep(64);
        }
        __threadfence();
    }
    __syncthreads();
}

// ---------------- build: deg -> barrier -> scan(+dinv) -> barrier -> fill ------
__global__ void __launch_bounds__(SCAN_BS, 1) build_kernel(
        const int* __restrict__ src, const int* __restrict__ dst) {
    int t = threadIdx.x, b = blockIdx.x;
    int gid = b * SCAN_BS + t;

    // reset this block's lookback state (used in phase 2, after barrier)
    if (t == 0) g_state[b] = 0ull;

    // phase 1: degree + per-edge rank; 16 contiguous edges/thread, int4 loads,
    // 16 independent atomics in flight (800000 = 50000 * 16 exactly)
    {
        int e0 = gid * 16;
        if (e0 < N_EDGES) {
            #pragma unroll
            for (int q = 0; q < 4; q++) {
                int4 d = *(const int4*)&dst[e0 + q * 4];
                int4 r;
                r.x = ((unsigned)d.x < N_NODES) ? atomicAdd(&g_degi[d.x], 1) : 0;
                r.y = ((unsigned)d.y < N_NODES) ? atomicAdd(&g_degi[d.y], 1) : 0;
                r.z = ((unsigned)d.z < N_NODES) ? atomicAdd(&g_degi[d.z], 1) : 0;
                r.w = ((unsigned)d.w < N_NODES) ? atomicAdd(&g_degi[d.w], 1) : 0;
                *(int4*)&g_rank[e0 + q * 4] = r;
            }
        }
    }
    grid_barrier(0);

    // phase 2: shfl-scan of degrees + dinv + re-zero degi; decoupled lookback
    __shared__ int warp_tot[16];
    __shared__ int s_excl;
    int lane = t & 31, wid = t >> 5;
    int i = gid;
    int s = (i < N_NODES) ? g_degi[i] : 0;
    if (i < N_NODES) {
        g_dinv[i] = rsqrtf((float)s + 1.0f);
        g_degi[i] = 0;                          // ready for next call
    }
    int v = s;
    #pragma unroll
    for (int off = 1; off < 32; off <<= 1) {
        int n = __shfl_up_sync(0xffffffff, v, off);
        if (lane >= off) v += n;
    }
    if (lane == 31) warp_tot[wid] = v;
    __syncthreads();
    if (wid == 0) {
        int wv = (lane < 16) ? warp_tot[lane] : 0;
        #pragma unroll
        for (int off = 1; off < 16; off <<= 1) {
            int n = __shfl_up_sync(0xffffffff, wv, off);
            if (lane >= off) wv += n;
        }
        if (lane < 16) warp_tot[lane] = wv;
    }
    __syncthreads();
    int incl = v + ((wid > 0) ? warp_tot[wid - 1] : 0);
    int total = warp_tot[15];

    if (t == 0) {
        if (b == 0) {
            atomicExch(&g_state[0], (2ull << 32) | (unsigned)total);
            s_excl = 0;
        } else {
            atomicExch(&g_state[b], (1ull << 32) | (unsigned)total);
            int excl = 0, idx = b - 1;
            while (true) {
                unsigned long long st = atomicAdd(&g_state[idx], 0ull);
                unsigned flag = (unsigned)(st >> 32);
                if (flag == 0u) { __nanosleep(20); continue; }
                excl += (int)(unsigned)st;
                if (flag == 2u) break;
                idx--;
            }
            atomicExch(&g_state[b], (2ull << 32) | (unsigned)(excl + total));
            s_excl = excl;
        }
    }
    __syncthreads();
    if (i < N_NODES) g_rowstart[i] = incl - s + s_excl;
    if (i == 0) g_rowstart[N_NODES] = N_EDGES;
    grid_barrier(1);

    // phase 3: atomic-free fill (16 contiguous edges/thread, int4 loads)
    {
        int e0 = gid * 16;
        if (e0 < N_EDGES) {
            #pragma unroll
            for (int q = 0; q < 4; q++) {
                int e4 = e0 + q * 4;
                int4 d = *(const int4*)&dst[e4];
                int4 sv = *(const int4*)&src[e4];
                int4 r = *(const int4*)&g_rank[e4];
                if ((unsigned)d.x < N_NODES && (unsigned)sv.x < N_NODES)
                    g_csr[g_rowstart[d.x] + r.x] = sv.x;
                if ((unsigned)d.y < N_NODES && (unsigned)sv.y < N_NODES)
                    g_csr[g_rowstart[d.y] + r.y] = sv.y;
                if ((unsigned)d.z < N_NODES && (unsigned)sv.z < N_NODES)
                    g_csr[g_rowstart[d.z] + r.z] = sv.z;
                if ((unsigned)d.w < N_NODES && (unsigned)sv.w < N_NODES)
                    g_csr[g_rowstart[d.w] + r.w] = sv.w;
            }
        }
    }
}

// ---------------- precompute c2 = W2 @ Wfc (coalesced), cbias ------------------
__global__ void wfc_kernel(const float* __restrict__ W2, const float* __restrict__ b2,
                           const float* __restrict__ Wfc, const float* __restrict__ bfc) {
    int tid = threadIdx.x;               // 512 threads
    int f = tid >> 2, j = tid & 3;       // 4 threads per feature
    float c0 = 0.f, c1 = 0.f;
    const float* wp = &W2[f * OUT_DIM + j * 16];
    #pragma unroll
    for (int q = 0; q < 4; q++) {
        float4 w = *(const float4*)&wp[q * 4];
        int kb = j * 16 + q * 4;
        c0 = fmaf(w.x, __ldg(&Wfc[(kb + 0) * 2 + 0]), c0);
        c1 = fmaf(w.x, __ldg(&Wfc[(kb + 0) * 2 + 1]), c1);
        c0 = fmaf(w.y, __ldg(&Wfc[(kb + 1) * 2 + 0]), c0);
        c1 = fmaf(w.y, __ldg(&Wfc[(kb + 1) * 2 + 1]), c1);
        c0 = fmaf(w.z, __ldg(&Wfc[(kb + 2) * 2 + 0]), c0);
        c1 = fmaf(w.z, __ldg(&Wfc[(kb + 2) * 2 + 1]), c1);
        c0 = fmaf(w.w, __ldg(&Wfc[(kb + 3) * 2 + 0]), c0);
        c1 = fmaf(w.w, __ldg(&Wfc[(kb + 3) * 2 + 1]), c1);
    }
    c0 += __shfl_xor_sync(0xffffffff, c0, 1);
    c0 += __shfl_xor_sync(0xffffffff, c0, 2);
    c1 += __shfl_xor_sync(0xffffffff, c1, 1);
    c1 += __shfl_xor_sync(0xffffffff, c1, 2);
    if (j == 0) {
        g_c2[f * 2 + 0] = c0;
        g_c2[f * 2 + 1] = c1;
    }
    if (tid < 2) {
        float acc = bfc[tid];
        for (int k = 0; k < OUT_DIM; k++) acc = fmaf(b2[k], Wfc[k * 2 + tid], acc);
        g_cbias[tid] = acc;
    }
}

// ---------------- gemm1: wmma fp16 (fp32 accum), 128x128 tile ------------------
#define GLDA 136
__global__ void __launch_bounds__(256, 1) gemm1_kernel(
        const float* __restrict__ x, const float* __restrict__ W1) {
    extern __shared__ char smem[];
    __half* Ah = (__half*)smem;
    __half* Bh = (__half*)(smem + 128 * GLDA * 2);
    float*  Cs = (float*)smem;

    const int tid = threadIdx.x;         // 256
    const int row0 = blockIdx.x * 128;

    #pragma unroll
    for (int l = 0; l < 16; l++) {
        int idx = (tid + l * 256) * 4;   // float4 granularity
        int r = idx >> 7, c = idx & 127;
        float4 fa = make_float4(0.f, 0.f, 0.f, 0.f);
        if (row0 + r < N_NODES) fa = *(const float4*)&x[(size_t)(row0 + r) * 128 + c];
        __half2 a0 = __float22half2_rn(make_float2(fa.x, fa.y));
        __half2 a1 = __float22half2_rn(make_float2(fa.z, fa.w));
        *(uint2*)&Ah[r * GLDA + c] = make_uint2(*(unsigned*)&a0, *(unsigned*)&a1);
        float4 fb = *(const float4*)&W1[(size_t)r * 128 + c];
        __half2 b0 = __float22half2_rn(make_float2(fb.x, fb.y));
        __half2 b1 = __float22half2_rn(make_float2(fb.z, fb.w));
        *(uint2*)&Bh[r * GLDA + c] = make_uint2(*(unsigned*)&b0, *(unsigned*)&b1);
    }
    __syncthreads();

    const int wid = tid >> 5;
    const int wm = wid & 1, wn = wid >> 1;
    wmma::fragment<wmma::accumulator, 16, 16, 16, float> acc[4][2];
    #pragma unroll
    for (int i = 0; i < 4; i++)
        #pragma unroll
        for (int j = 0; j < 2; j++)
            wmma::fill_fragment(acc[i][j], 0.f);

    #pragma unroll
    for (int k = 0; k < 8; k++) {
        wmma::fragment<wmma::matrix_a, 16, 16, 16, __half, wmma::row_major> af[4];
        wmma::fragment<wmma::matrix_b, 16, 16, 16, __half, wmma::row_major> bf[2];
        #pragma unroll
        for (int i = 0; i < 4; i++)
            wmma::load_matrix_sync(af[i], Ah + (wm * 64 + i * 16) * GLDA + k * 16, GLDA);
        #pragma unroll
        for (int j = 0; j < 2; j++)
            wmma::load_matrix_sync(bf[j], Bh + (k * 16) * GLDA + wn * 32 + j * 16, GLDA);
        #pragma unroll
        for (int i = 0; i < 4; i++)
            #pragma unroll
            for (int j = 0; j < 2; j++)
                wmma::mma_sync(acc[i][j], af[i], bf[j], acc[i][j]);
    }
    __syncthreads();   // done reading Ah/Bh; reuse smem as C

    #pragma unroll
    for (int i = 0; i < 4; i++)
        #pragma unroll
        for (int j = 0; j < 2; j++)
            wmma::store_matrix_sync(Cs + (wm * 64 + i * 16) * 128 + wn * 32 + j * 16,
                                    acc[i][j], 128, wmma::mem_row_major);
    __syncthreads();

    #pragma unroll
    for (int l = 0; l < 16; l++) {
        int idx = (tid + l * 256) * 4;
        int r = idx >> 7, c = idx & 127;
        if (row0 + r < N_NODES) {
            float4 f = *(const float4*)&Cs[r * 128 + c];
            __half2 h0 = __float22half2_rn(make_float2(f.x, f.y));
            __half2 h1 = __float22half2_rn(make_float2(f.z, f.w));
            *(uint2*)&g_xwh[(size_t)(row0 + r) * 128 + c] =
                make_uint2(*(unsigned*)&h0, *(unsigned*)&h1);
        }
    }
}

// ---------------- gather1 v2: 2 edges/warp-iter, 16B loads, fused epilogue -----
// Lanes 0-15 handle even edges, 16-31 odd edges; each lane owns 8 features.
__global__ void gather1_kernel(const float* __restrict__ b1) {
    int w = (blockIdx.x * blockDim.x + threadIdx.x) >> 5;
    int lane = threadIdx.x & 31;
    if (w >= N_NODES) return;
    int beg = g_rowstart[w];
    int end = g_rowstart[w + 1];
    const int fl = lane & 15;
    const int half = lane >> 4;
    const int fo = fl * 8;                      // this lane's 8-feature offset

    float dself = g_dinv[w];
    float acc[8];
    if (half == 0) {
        float sv[8];
        ldg_half8(&g_xwh[(size_t)w * HID_DIM + fo], sv);
        #pragma unroll
        for (int j = 0; j < 8; j++) acc[j] = sv[j] * dself;
    } else {
        #pragma unroll
        for (int j = 0; j < 8; j++) acc[j] = 0.f;
    }

    int e = beg;
    for (; e + 7 < end; e += 8) {               // 8 edges per warp batch (4/lane)
        int sI[4]; float dv[4]; float v[4][8];
        #pragma unroll
        for (int i = 0; i < 4; i++) sI[i] = __ldg(&g_csr[e + half + 2 * i]);
        #pragma unroll
        for (int i = 0; i < 4; i++) dv[i] = __ldg(&g_dinv[sI[i]]);
        #pragma unroll
        for (int i = 0; i < 4; i++) ldg_half8(&g_xwh[(size_t)sI[i] * HID_DIM + fo], v[i]);
        #pragma unroll
        for (int i = 0; i < 4; i++)
            #pragma unroll
            for (int j = 0; j < 8; j++) acc[j] = fmaf(v[i][j], dv[i], acc[j]);
    }
    for (; e + half < end; e += 2) {            // tail, parity-split
        int s0 = __ldg(&g_csr[e + half]);
        float d0 = __ldg(&g_dinv[s0]);
        float v0[8];
        ldg_half8(&g_xwh[(size_t)s0 * HID_DIM + fo], v0);
        #pragma unroll
        for (int j = 0; j < 8; j++) acc[j] = fmaf(v0[j], d0, acc[j]);
    }

    // combine even/odd halves (features must be complete before relu)
    #pragma unroll
    for (int j = 0; j < 8; j++)
        acc[j] += __shfl_xor_sync(0xffffffff, acc[j], 16);

    // relu(dself*acc + b1)
    float4 bb0 = *(const float4*)&b1[fo];
    float4 bb1 = *(const float4*)&b1[fo + 4];
    float r[8];
    r[0] = fmaxf(fmaf(dself, acc[0], bb0.x), 0.f);
    r[1] = fmaxf(fmaf(dself, acc[1], bb0.y), 0.f);
    r[2] = fmaxf(fmaf(dself, acc[2], bb0.z), 0.f);
    r[3] = fmaxf(fmaf(dself, acc[3], bb0.w), 0.f);
    r[4] = fmaxf(fmaf(dself, acc[4], bb1.x), 0.f);
    r[5] = fmaxf(fmaf(dself, acc[5], bb1.y), 0.f);
    r[6] = fmaxf(fmaf(dself, acc[6], bb1.z), 0.f);
    r[7] = fmaxf(fmaf(dself, acc[7], bb1.w), 0.f);

    // z = h_row @ c2 (this lane's 8 features)
    float z0 = 0.f, z1 = 0.f;
    #pragma unroll
    for (int j = 0; j < 8; j += 2) {
        float4 c = *(const float4*)&g_c2[(fo + j) * 2];   // 2 features' (c0,c1)
        z0 = fmaf(r[j],     c.x, z0); z1 = fmaf(r[j],     c.y, z1);
        z0 = fmaf(r[j + 1], c.z, z0); z1 = fmaf(r[j + 1], c.w, z1);
    }
    // reduce across the 16 feature lanes only (halves are duplicates)
    #pragma unroll
    for (int off = 8; off > 0; off >>= 1) {
        z0 += __shfl_xor_sync(0xffffffff, z0, off);
        z1 += __shfl_xor_sync(0xffffffff, z1, off);
    }
    if (lane == 0)
        *(float2*)&g_z[w * 2] = make_float2(z0 * dself, z1 * dself);
}

// ---------------- gather2': tiny float2 aggregation + leaky --------------------
__global__ void gather2_kernel(float* __restrict__ out) {
    int w = (blockIdx.x * blockDim.x + threadIdx.x) >> 5;
    int lane = threadIdx.x & 31;
    if (w >= N_NODES) return;
    int beg = g_rowstart[w];
    int end = g_rowstart[w + 1];

    float ax = 0.f, ay = 0.f;
    for (int e = beg + lane; e < end; e += 32) {
        int s = __ldg(&g_csr[e]);
        float2 v = *(const float2*)&g_z[s * 2];
        ax += v.x; ay += v.y;
    }
    #pragma unroll
    for (int off = 16; off > 0; off >>= 1) {
        ax += __shfl_xor_sync(0xffffffff, ax, off);
        ay += __shfl_xor_sync(0xffffffff, ay, off);
    }
    if (lane == 0) {
        float di = g_dinv[w];
        float2 zs = *(const float2*)&g_z[w * 2];
        float o0 = fmaf(di, ax + zs.x, g_cbias[0]);
        float o1 = fmaf(di, ay + zs.y, g_cbias[1]);
        out[w * 2 + 0] = (o0 > 0.f) ? o0 : 0.01f * o0;
        out[w * 2 + 1] = (o1 > 0.f) ? o1 : 0.01f * o1;
    }
}

// ---------------- launch -------------------------------------------------------
// Arms: s_side = build (one persistent kernel), s_w = wfc, default = gemm1.
extern "C" void kernel_launch(void* const* d_in, const int* in_sizes, int n_in,
                              void* d_out, int out_size) {
    const float* x   = (const float*)d_in[0];
    const int*   ei  = (const int*)d_in[1];   // JAX default: int64 demoted to int32
    const float* W1  = (const float*)d_in[2];
    const float* b1  = (const float*)d_in[3];
    const float* W2  = (const float*)d_in[4];
    const float* b2  = (const float*)d_in[5];
    const float* Wfc = (const float*)d_in[6];
    const float* bfc = (const float*)d_in[7];
    float* out = (float*)d_out;

    const int* src = ei;
    const int* dst = ei + N_EDGES;

    static cudaStream_t s_side = nullptr, s_w = nullptr;
    static cudaEvent_t  e_fork = nullptr, e_join = nullptr, e_wfc = nullptr;
    if (s_side == nullptr) {
        cudaStreamCreateWithFlags(&s_side, cudaStreamNonBlocking);
        cudaStreamCreateWithFlags(&s_w,    cudaStreamNonBlocking);
        cudaEventCreateWithFlags(&e_fork, cudaEventDisableTiming);
        cudaEventCreateWithFlags(&e_join, cudaEventDisableTiming);
        cudaEventCreateWithFlags(&e_wfc,  cudaEventDisableTiming);
        cudaFuncSetAttribute(gemm1_kernel,
                             cudaFuncAttributeMaxDynamicSharedMemorySize,
                             128 * GLDA * 2 * 2);      // 69632 B
    }
    const int GEMM_SMEM = 128 * GLDA * 2 * 2;

    // fork side streams off the (captured) default stream
    cudaEventRecord(e_fork, 0);
    cudaStreamWaitEvent(s_side, e_fork, 0);
    cudaStreamWaitEvent(s_w,    e_fork, 0);

    // side stream: one persistent CSR-build kernel
    build_kernel<<<SCAN_NB, SCAN_BS, 0, s_side>>>(src, dst);
    cudaEventRecord(e_join, s_side);

    // wfc stream: tiny precompute
    wfc_kernel<<<1, 512, 0, s_w>>>(W2, b2, Wfc, bfc);
    cudaEventRecord(e_wfc, s_w);

    // default stream: tensor-core gemm1
    gemm1_kernel<<<(N_NODES + 127) / 128, 256, GEMM_SMEM>>>(x, W1);
    cudaStreamWaitEvent(0, e_join, 0);
    cudaStreamWaitEvent(0, e_wfc, 0);

    // fused layer-1 aggregation + relu + (W2 Wfc) projection + dinv scale
    gather1_kernel<<<(N_NODES * 32 + 255) / 256, 256>>>(b1);

    // tiny layer-2 aggregation + FC bias + leaky relu
    gather2_kernel<<<(N_NODES * 32 + 255) / 256, 256>>>(out);
}

// round 17
// speedup vs baseline: 1.0271x; 1.0271x over previous
#include <cuda_runtime.h>
#include <cuda_fp16.h>
#include <cuda_bf16.h>
#include <mma.h>
#include <cstdint>

using namespace nvcuda;

#define N_NODES 50000
#define N_EDGES 800000
#define IN_DIM  128
#define HID_DIM 128
#define OUT_DIM 64

#define SCAN_BS   512
#define SCAN_NB   ((N_NODES + SCAN_BS - 1) / SCAN_BS)   // 98
#define BUILD_T   (SCAN_NB * SCAN_BS)                    // 50176 threads grid-wide

// ---------------- scratch (device globals: no allocation allowed) -------------
// Only referenced from DEVICE code (R5 lesson).
// Cross-call invariants (graph replays run the identical sequence):
//   g_degi  : zero at load; build phase-2 re-zeroes after reading.
//   g_state : build resets its own slot at kernel start (before barrier 1).
//   g_barctr/g_barrel : monotonic epoch barrier; never reset.
__device__ __align__(16) int                g_degi    [N_NODES];
__device__ __align__(16) float              g_dinv    [N_NODES];
__device__ __align__(16) int                g_rowstart[N_NODES + 1];
__device__ __align__(16) int                g_rank    [N_EDGES];
__device__ __align__(16) int2               g_csrd    [N_EDGES];   // (src, dinv[src] bits)
__device__ __align__(16) unsigned long long g_state   [SCAN_NB];
__device__ unsigned g_barctr[2];
__device__ unsigned g_barrel[2];
__device__ __align__(16) __half             g_xwh     [N_NODES * HID_DIM];  // x@W1, fp16
__device__ __align__(16) float              g_c2      [HID_DIM * 2];        // W2 @ Wfc
__device__ __align__(16) float              g_cbias   [2];                  // b2@Wfc + bfc
__device__ __align__(16) float              g_z       [N_NODES * 2];

// ---------------- helpers -------------------------------------------------------
// load 4 halves (8B) and widen to float4
__device__ __forceinline__ float4 ldg_half4(const __half* p) {
    uint2 u = __ldg(reinterpret_cast<const uint2*>(p));
    __half2 h0 = *reinterpret_cast<__half2*>(&u.x);
    __half2 h1 = *reinterpret_cast<__half2*>(&u.y);
    float2 f0 = __half22float2(h0);
    float2 f1 = __half22float2(h1);
    return make_float4(f0.x, f0.y, f1.x, f1.y);
}

// monotonic epoch grid barrier: replay-safe (no resets), deadlock-free for
// co-resident grids (98 blocks <= 148 SMs).
__device__ __forceinline__ void grid_barrier(int i) {
    __syncthreads();
    if (threadIdx.x == 0) {
        __threadfence();
        unsigned old = atomicAdd(&g_barctr[i], 1u);
        unsigned epoch = old / SCAN_NB;
        if (old % SCAN_NB == SCAN_NB - 1) {
            atomicAdd(&g_barrel[i], 1u);               // release this epoch
        } else {
            while (*(volatile unsigned*)&g_barrel[i] <= epoch) __nanosleep(64);
        }
        __threadfence();
    }
    __syncthreads();
}

// ---------------- build: deg -> barrier -> scan(+dinv) -> barrier -> fill ------
__global__ void __launch_bounds__(SCAN_BS, 1) build_kernel(
        const int* __restrict__ src, const int* __restrict__ dst) {
    int t = threadIdx.x, b = blockIdx.x;
    int gid = b * SCAN_BS + t;

    // reset this block's lookback state (used in phase 2, after barrier)
    if (t == 0) g_state[b] = 0ull;

    // phase 1: degree + per-edge rank; 16 contiguous edges/thread, int4 loads,
    // 16 independent atomics in flight (800000 = 50000 * 16 exactly)
    {
        int e0 = gid * 16;
        if (e0 < N_EDGES) {
            #pragma unroll
            for (int q = 0; q < 4; q++) {
                int4 d = *(const int4*)&dst[e0 + q * 4];
                int4 r;
                r.x = ((unsigned)d.x < N_NODES) ? atomicAdd(&g_degi[d.x], 1) : 0;
                r.y = ((unsigned)d.y < N_NODES) ? atomicAdd(&g_degi[d.y], 1) : 0;
                r.z = ((unsigned)d.z < N_NODES) ? atomicAdd(&g_degi[d.z], 1) : 0;
                r.w = ((unsigned)d.w < N_NODES) ? atomicAdd(&g_degi[d.w], 1) : 0;
                *(int4*)&g_rank[e0 + q * 4] = r;
            }
        }
    }
    grid_barrier(0);

    // phase 2: shfl-scan of degrees + dinv + re-zero degi; decoupled lookback
    __shared__ int warp_tot[16];
    __shared__ int s_excl;
    int lane = t & 31, wid = t >> 5;
    int i = gid;
    int s = (i < N_NODES) ? g_degi[i] : 0;
    if (i < N_NODES) {
        g_dinv[i] = rsqrtf((float)s + 1.0f);
        g_degi[i] = 0;                          // ready for next call
    }
    int v = s;
    #pragma unroll
    for (int off = 1; off < 32; off <<= 1) {
        int n = __shfl_up_sync(0xffffffff, v, off);
        if (lane >= off) v += n;
    }
    if (lane == 31) warp_tot[wid] = v;
    __syncthreads();
    if (wid == 0) {
        int wv = (lane < 16) ? warp_tot[lane] : 0;
        #pragma unroll
        for (int off = 1; off < 16; off <<= 1) {
            int n = __shfl_up_sync(0xffffffff, wv, off);
            if (lane >= off) wv += n;
        }
        if (lane < 16) warp_tot[lane] = wv;
    }
    __syncthreads();
    int incl = v + ((wid > 0) ? warp_tot[wid - 1] : 0);
    int total = warp_tot[15];

    if (t == 0) {
        if (b == 0) {
            atomicExch(&g_state[0], (2ull << 32) | (unsigned)total);
            s_excl = 0;
        } else {
            atomicExch(&g_state[b], (1ull << 32) | (unsigned)total);
            int excl = 0, idx = b - 1;
            while (true) {
                unsigned long long st = atomicAdd(&g_state[idx], 0ull);
                unsigned flag = (unsigned)(st >> 32);
                if (flag == 0u) { __nanosleep(20); continue; }
                excl += (int)(unsigned)st;
                if (flag == 2u) break;
                idx--;
            }
            atomicExch(&g_state[b], (2ull << 32) | (unsigned)(excl + total));
            s_excl = excl;
        }
    }
    __syncthreads();
    if (i < N_NODES) g_rowstart[i] = incl - s + s_excl;
    if (i == 0) g_rowstart[N_NODES] = N_EDGES;
    grid_barrier(1);

    // phase 3: atomic-free fill; slot gets (src, dinv[src]) packed as int2
    {
        int e0 = gid * 16;
        if (e0 < N_EDGES) {
            #pragma unroll
            for (int q = 0; q < 4; q++) {
                int e4 = e0 + q * 4;
                int4 d = *(const int4*)&dst[e4];
                int4 sv = *(const int4*)&src[e4];
                int4 r = *(const int4*)&g_rank[e4];
                if ((unsigned)d.x < N_NODES && (unsigned)sv.x < N_NODES)
                    g_csrd[g_rowstart[d.x] + r.x] =
                        make_int2(sv.x, __float_as_int(g_dinv[sv.x]));
                if ((unsigned)d.y < N_NODES && (unsigned)sv.y < N_NODES)
                    g_csrd[g_rowstart[d.y] + r.y] =
                        make_int2(sv.y, __float_as_int(g_dinv[sv.y]));
                if ((unsigned)d.z < N_NODES && (unsigned)sv.z < N_NODES)
                    g_csrd[g_rowstart[d.z] + r.z] =
                        make_int2(sv.z, __float_as_int(g_dinv[sv.z]));
                if ((unsigned)d.w < N_NODES && (unsigned)sv.w < N_NODES)
                    g_csrd[g_rowstart[d.w] + r.w] =
                        make_int2(sv.w, __float_as_int(g_dinv[sv.w]));
            }
        }
    }
}

// ---------------- precompute c2 = W2 @ Wfc (coalesced), cbias ------------------
__global__ void wfc_kernel(const float* __restrict__ W2, const float* __restrict__ b2,
                           const float* __restrict__ Wfc, const float* __restrict__ bfc) {
    int tid = threadIdx.x;               // 512 threads
    int f = tid >> 2, j = tid & 3;       // 4 threads per feature
    float c0 = 0.f, c1 = 0.f;
    const float* wp = &W2[f * OUT_DIM + j * 16];
    #pragma unroll
    for (int q = 0; q < 4; q++) {
        float4 w = *(const float4*)&wp[q * 4];
        int kb = j * 16 + q * 4;
        c0 = fmaf(w.x, __ldg(&Wfc[(kb + 0) * 2 + 0]), c0);
        c1 = fmaf(w.x, __ldg(&Wfc[(kb + 0) * 2 + 1]), c1);
        c0 = fmaf(w.y, __ldg(&Wfc[(kb + 1) * 2 + 0]), c0);
        c1 = fmaf(w.y, __ldg(&Wfc[(kb + 1) * 2 + 1]), c1);
        c0 = fmaf(w.z, __ldg(&Wfc[(kb + 2) * 2 + 0]), c0);
        c1 = fmaf(w.z, __ldg(&Wfc[(kb + 2) * 2 + 1]), c1);
        c0 = fmaf(w.w, __ldg(&Wfc[(kb + 3) * 2 + 0]), c0);
        c1 = fmaf(w.w, __ldg(&Wfc[(kb + 3) * 2 + 1]), c1);
    }
    c0 += __shfl_xor_sync(0xffffffff, c0, 1);
    c0 += __shfl_xor_sync(0xffffffff, c0, 2);
    c1 += __shfl_xor_sync(0xffffffff, c1, 1);
    c1 += __shfl_xor_sync(0xffffffff, c1, 2);
    if (j == 0) {
        g_c2[f * 2 + 0] = c0;
        g_c2[f * 2 + 1] = c1;
    }
    if (tid < 2) {
        float acc = bfc[tid];
        for (int k = 0; k < OUT_DIM; k++) acc = fmaf(b2[k], Wfc[k * 2 + tid], acc);
        g_cbias[tid] = acc;
    }
}

// ---------------- gemm1: wmma fp16 (fp32 accum), 128x128 tile ------------------
#define GLDA 136
__global__ void __launch_bounds__(256, 1) gemm1_kernel(
        const float* __restrict__ x, const float* __restrict__ W1) {
    extern __shared__ char smem[];
    __half* Ah = (__half*)smem;
    __half* Bh = (__half*)(smem + 128 * GLDA * 2);
    float*  Cs = (float*)smem;

    const int tid = threadIdx.x;         // 256
    const int row0 = blockIdx.x * 128;

    #pragma unroll
    for (int l = 0; l < 16; l++) {
        int idx = (tid + l * 256) * 4;   // float4 granularity
        int r = idx >> 7, c = idx & 127;
        float4 fa = make_float4(0.f, 0.f, 0.f, 0.f);
        if (row0 + r < N_NODES) fa = *(const float4*)&x[(size_t)(row0 + r) * 128 + c];
        __half2 a0 = __float22half2_rn(make_float2(fa.x, fa.y));
        __half2 a1 = __float22half2_rn(make_float2(fa.z, fa.w));
        *(uint2*)&Ah[r * GLDA + c] = make_uint2(*(unsigned*)&a0, *(unsigned*)&a1);
        float4 fb = *(const float4*)&W1[(size_t)r * 128 + c];
        __half2 b0 = __float22half2_rn(make_float2(fb.x, fb.y));
        __half2 b1 = __float22half2_rn(make_float2(fb.z, fb.w));
        *(uint2*)&Bh[r * GLDA + c] = make_uint2(*(unsigned*)&b0, *(unsigned*)&b1);
    }
    __syncthreads();

    const int wid = tid >> 5;
    const int wm = wid & 1, wn = wid >> 1;
    wmma::fragment<wmma::accumulator, 16, 16, 16, float> acc[4][2];
    #pragma unroll
    for (int i = 0; i < 4; i++)
        #pragma unroll
        for (int j = 0; j < 2; j++)
            wmma::fill_fragment(acc[i][j], 0.f);

    #pragma unroll
    for (int k = 0; k < 8; k++) {
        wmma::fragment<wmma::matrix_a, 16, 16, 16, __half, wmma::row_major> af[4];
        wmma::fragment<wmma::matrix_b, 16, 16, 16, __half, wmma::row_major> bf[2];
        #pragma unroll
        for (int i = 0; i < 4; i++)
            wmma::load_matrix_sync(af[i], Ah + (wm * 64 + i * 16) * GLDA + k * 16, GLDA);
        #pragma unroll
        for (int j = 0; j < 2; j++)
            wmma::load_matrix_sync(bf[j], Bh + (k * 16) * GLDA + wn * 32 + j * 16, GLDA);
        #pragma unroll
        for (int i = 0; i < 4; i++)
            #pragma unroll
            for (int j = 0; j < 2; j++)
                wmma::mma_sync(acc[i][j], af[i], bf[j], acc[i][j]);
    }
    __syncthreads();   // done reading Ah/Bh; reuse smem as C

    #pragma unroll
    for (int i = 0; i < 4; i++)
        #pragma unroll
        for (int j = 0; j < 2; j++)
            wmma::store_matrix_sync(Cs + (wm * 64 + i * 16) * 128 + wn * 32 + j * 16,
                                    acc[i][j], 128, wmma::mem_row_major);
    __syncthreads();

    #pragma unroll
    for (int l = 0; l < 16; l++) {
        int idx = (tid + l * 256) * 4;
        int r = idx >> 7, c = idx & 127;
        if (row0 + r < N_NODES) {
            float4 f = *(const float4*)&Cs[r * 128 + c];
            __half2 h0 = __float22half2_rn(make_float2(f.x, f.y));
            __half2 h1 = __float22half2_rn(make_float2(f.z, f.w));
            *(uint2*)&g_xwh[(size_t)(row0 + r) * 128 + c] =
                make_uint2(*(unsigned*)&h0, *(unsigned*)&h1);
        }
    }
}

// ---------------- gather1: warp/node, 1 row per load instr, packed csrd --------
// h_row = relu( dinv_d*(sum_s xw[s]*dinv[s] + xw[d]*dinv[d]) + b1 )
// z'[d] = (h_row @ c2) * dinv_d
__global__ void gather1_kernel(const float* __restrict__ b1) {
    int w = (blockIdx.x * blockDim.x + threadIdx.x) >> 5;
    int lane = threadIdx.x & 31;
    if (w >= N_NODES) return;
    int beg = g_rowstart[w];
    int end = g_rowstart[w + 1];
    const int fo = 4 * lane;

    float dself = g_dinv[w];
    float4 self = ldg_half4(&g_xwh[(size_t)w * HID_DIM + fo]);
    float4 acc;
    acc.x = self.x * dself; acc.y = self.y * dself;
    acc.z = self.z * dself; acc.w = self.w * dself;

    int e = beg;
    for (; e + 7 < end; e += 8) {
        int2 sd[8]; float4 v[8];
        #pragma unroll
        for (int i = 0; i < 8; i++) sd[i] = __ldg(&g_csrd[e + i]);   // (src, dinv)
        #pragma unroll
        for (int i = 0; i < 8; i++)
            v[i] = ldg_half4(&g_xwh[(size_t)sd[i].x * HID_DIM + fo]);
        #pragma unroll
        for (int i = 0; i < 8; i++) {
            float dv = __int_as_float(sd[i].y);
            acc.x = fmaf(v[i].x, dv, acc.x);
            acc.y = fmaf(v[i].y, dv, acc.y);
            acc.z = fmaf(v[i].z, dv, acc.z);
            acc.w = fmaf(v[i].w, dv, acc.w);
        }
    }
    for (; e < end; e++) {
        int2 sd = __ldg(&g_csrd[e]);
        float dv = __int_as_float(sd.y);
        float4 v0 = ldg_half4(&g_xwh[(size_t)sd.x * HID_DIM + fo]);
        acc.x = fmaf(v0.x, dv, acc.x); acc.y = fmaf(v0.y, dv, acc.y);
        acc.z = fmaf(v0.z, dv, acc.z); acc.w = fmaf(v0.w, dv, acc.w);
    }
    float4 bb = reinterpret_cast<const float4*>(b1)[lane];
    float4 r;
    r.x = fmaxf(fmaf(dself, acc.x, bb.x), 0.f);
    r.y = fmaxf(fmaf(dself, acc.y, bb.y), 0.f);
    r.z = fmaxf(fmaf(dself, acc.z, bb.z), 0.f);
    r.w = fmaxf(fmaf(dself, acc.w, bb.w), 0.f);

    float4 ca = *(const float4*)&g_c2[8 * lane];
    float4 cb = *(const float4*)&g_c2[8 * lane + 4];
    float z0 = r.x * ca.x + r.y * ca.z + r.z * cb.x + r.w * cb.z;
    float z1 = r.x * ca.y + r.y * ca.w + r.z * cb.y + r.w * cb.w;
    #pragma unroll
    for (int off = 16; off > 0; off >>= 1) {
        z0 += __shfl_xor_sync(0xffffffff, z0, off);
        z1 += __shfl_xor_sync(0xffffffff, z1, off);
    }
    if (lane == 0)
        *(float2*)&g_z[w * 2] = make_float2(z0 * dself, z1 * dself);
}

// ---------------- gather2': tiny float2 aggregation + leaky --------------------
__global__ void gather2_kernel(float* __restrict__ out) {
    int w = (blockIdx.x * blockDim.x + threadIdx.x) >> 5;
    int lane = threadIdx.x & 31;
    if (w >= N_NODES) return;
    int beg = g_rowstart[w];
    int end = g_rowstart[w + 1];

    float ax = 0.f, ay = 0.f;
    for (int e = beg + lane; e < end; e += 32) {
        int s = __ldg(&g_csrd[e]).x;
        float2 v = *(const float2*)&g_z[s * 2];
        ax += v.x; ay += v.y;
    }
    #pragma unroll
    for (int off = 16; off > 0; off >>= 1) {
        ax += __shfl_xor_sync(0xffffffff, ax, off);
        ay += __shfl_xor_sync(0xffffffff, ay, off);
    }
    if (lane == 0) {
        float di = g_dinv[w];
        float2 zs = *(const float2*)&g_z[w * 2];
        float o0 = fmaf(di, ax + zs.x, g_cbias[0]);
        float o1 = fmaf(di, ay + zs.y, g_cbias[1]);
        out[w * 2 + 0] = (o0 > 0.f) ? o0 : 0.01f * o0;
        out[w * 2 + 1] = (o1 > 0.f) ? o1 : 0.01f * o1;
    }
}

// ---------------- launch -------------------------------------------------------
// Arms: s_side = build (one persistent kernel), s_w = wfc, default = gemm1.
extern "C" void kernel_launch(void* const* d_in, const int* in_sizes, int n_in,
                              void* d_out, int out_size) {
    const float* x   = (const float*)d_in[0];
    const int*   ei  = (const int*)d_in[1];   // JAX default: int64 demoted to int32
    const float* W1  = (const float*)d_in[2];
    const float* b1  = (const float*)d_in[3];
    const float* W2  = (const float*)d_in[4];
    const float* b2  = (const float*)d_in[5];
    const float* Wfc = (const float*)d_in[6];
    const float* bfc = (const float*)d_in[7];
    float* out = (float*)d_out;

    const int* src = ei;
    const int* dst = ei + N_EDGES;

    static cudaStream_t s_side = nullptr, s_w = nullptr;
    static cudaEvent_t  e_fork = nullptr, e_join = nullptr, e_wfc = nullptr;
    if (s_side == nullptr) {
        cudaStreamCreateWithFlags(&s_side, cudaStreamNonBlocking);
        cudaStreamCreateWithFlags(&s_w,    cudaStreamNonBlocking);
        cudaEventCreateWithFlags(&e_fork, cudaEventDisableTiming);
        cudaEventCreateWithFlags(&e_join, cudaEventDisableTiming);
        cudaEventCreateWithFlags(&e_wfc,  cudaEventDisableTiming);
        cudaFuncSetAttribute(gemm1_kernel,
                             cudaFuncAttributeMaxDynamicSharedMemorySize,
                             128 * GLDA * 2 * 2);      // 69632 B
    }
    const int GEMM_SMEM = 128 * GLDA * 2 * 2;

    // fork side streams off the (captured) default stream
    cudaEventRecord(e_fork, 0);
    cudaStreamWaitEvent(s_side, e_fork, 0);
    cudaStreamWaitEvent(s_w,    e_fork, 0);

    // side stream: one persistent CSR-build kernel
    build_kernel<<<SCAN_NB, SCAN_BS, 0, s_side>>>(src, dst);
    cudaEventRecord(e_join, s_side);

    // wfc stream: tiny precompute
    wfc_kernel<<<1, 512, 0, s_w>>>(W2, b2, Wfc, bfc);
    cudaEventRecord(e_wfc, s_w);

    // default stream: tensor-core gemm1
    gemm1_kernel<<<(N_NODES + 127) / 128, 256, GEMM_SMEM>>>(x, W1);
    cudaStreamWaitEvent(0, e_join, 0);
    cudaStreamWaitEvent(0, e_wfc, 0);

    // fused layer-1 aggregation + relu + (W2 Wfc) projection + dinv scale
    gather1_kernel<<<(N_NODES * 32 + 255) / 256, 256>>>(b1);

    // tiny layer-2 aggregation + FC bias + leaky relu
    gather2_kernel<<<(N_NODES * 32 + 255) / 256, 256>>>(out);
}